// round 2
// baseline (speedup 1.0000x reference)
#include <cuda_runtime.h>
#include <cuda_bf16.h>
#include <stdint.h>

// Scratch (no cudaMalloc allowed): packed class table + global accumulator.
#define MAX_NODES 131072
__device__ unsigned char g_cls[MAX_NODES];
__device__ double g_sum;

// ---------------------------------------------------------------------------
// Kernel 1: pack int32 node classes -> uint8 table, zero the accumulator.
// ---------------------------------------------------------------------------
__global__ void pack_classes_kernel(const int* __restrict__ node_classes,
                                    int n_nodes) {
    int i = blockIdx.x * blockDim.x + threadIdx.x;
    if (i == 0) g_sum = 0.0;
    if (i < n_nodes) {
        g_cls[i] = (unsigned char)node_classes[i];
    }
}

// ---------------------------------------------------------------------------
// Kernel 2: main edge loop.
//   dyn smem layout: [0, n_nodes) uint8 class table, then (4B aligned) C*C floats.
// ---------------------------------------------------------------------------
__global__ void __launch_bounds__(512)
edge_loss_kernel(const float* __restrict__ edge_scores,
                 const int* __restrict__ edge_indices,
                 const float* __restrict__ adj,
                 int n_edges, int n_nodes, int C) {
    extern __shared__ unsigned char smem[];
    int adj_off = (n_nodes + 3) & ~3;
    float* s_adj = (float*)(smem + adj_off);

    int tid = threadIdx.x;
    int nthreads = blockDim.x;

    // Stage class table into shared (vectorized 16B copies + byte tail).
    int n16 = n_nodes >> 4;
    const uint4* src16 = (const uint4*)g_cls;
    uint4* dst16 = (uint4*)smem;
    for (int i = tid; i < n16; i += nthreads) dst16[i] = src16[i];
    for (int i = (n16 << 4) + tid; i < n_nodes; i += nthreads) smem[i] = g_cls[i];
    // Stage adjacency.
    for (int i = tid; i < C * C; i += nthreads) s_adj[i] = adj[i];
    __syncthreads();

    const int* src_idx = edge_indices;            // row 0
    const int* dst_idx = edge_indices + n_edges;  // row 1

    int nq = n_edges >> 2;  // groups of 4 edges
    int gtid = blockIdx.x * nthreads + tid;
    int gstride = gridDim.x * nthreads;
    int guard = n_nodes - 1;

    float acc = 0.0f;

    #pragma unroll 2
    for (int q = gtid; q < nq; q += gstride) {
        int4 s4 = *(const int4*)(src_idx + 4 * q);
        int4 d4 = *(const int4*)(dst_idx + 4 * q);
        float4 sc = *(const float4*)(edge_scores + 4 * q);

        int a0 = smem[min(s4.x, guard)];
        int b0 = smem[min(d4.x, guard)];
        int a1 = smem[min(s4.y, guard)];
        int b1 = smem[min(d4.y, guard)];
        int a2 = smem[min(s4.z, guard)];
        int b2 = smem[min(d4.z, guard)];
        int a3 = smem[min(s4.w, guard)];
        int b3 = smem[min(d4.w, guard)];

        float y0 = s_adj[a0 * C + b0];
        float y1 = s_adj[a1 * C + b1];
        float y2 = s_adj[a2 * C + b2];
        float y3 = s_adj[a3 * C + b3];

        // softplus(s) - s*y = max(s,0) + log1p(exp(-|s|)) - s*y
        float s0 = sc.x, s1 = sc.y, s2 = sc.z, s3 = sc.w;
        acc += fmaxf(s0, 0.0f) - s0 * y0 + log1pf(__expf(-fabsf(s0)));
        acc += fmaxf(s1, 0.0f) - s1 * y1 + log1pf(__expf(-fabsf(s1)));
        acc += fmaxf(s2, 0.0f) - s2 * y2 + log1pf(__expf(-fabsf(s2)));
        acc += fmaxf(s3, 0.0f) - s3 * y3 + log1pf(__expf(-fabsf(s3)));
    }

    // Tail edges (n_edges % 4), handled by thread 0 of block 0.
    if (gtid == 0) {
        for (int e = nq << 2; e < n_edges; e++) {
            int a = smem[min(src_idx[e], guard)];
            int b = smem[min(dst_idx[e], guard)];
            float y = s_adj[a * C + b];
            float s = edge_scores[e];
            acc += fmaxf(s, 0.0f) - s * y + log1pf(__expf(-fabsf(s)));
        }
    }

    // Block reduction: warp shuffle -> shared -> one double atomic per block.
    __shared__ float red[16];
    int lane = tid & 31;
    int wid = tid >> 5;
    #pragma unroll
    for (int off = 16; off > 0; off >>= 1)
        acc += __shfl_xor_sync(0xFFFFFFFFu, acc, off);
    if (lane == 0) red[wid] = acc;
    __syncthreads();
    if (wid == 0) {
        int nw = nthreads >> 5;
        float v = (lane < nw) ? red[lane] : 0.0f;
        #pragma unroll
        for (int off = 8; off > 0; off >>= 1)
            v += __shfl_xor_sync(0xFFFFFFFFu, v, off);
        if (lane == 0) atomicAdd(&g_sum, (double)v);
    }
}

// ---------------------------------------------------------------------------
// Kernel 3: finalize mean.
// ---------------------------------------------------------------------------
__global__ void finalize_kernel(float* __restrict__ out, int n_edges) {
    out[0] = (float)(g_sum / (double)n_edges);
}

extern "C" void kernel_launch(void* const* d_in, const int* in_sizes, int n_in,
                              void* d_out, int out_size) {
    // Inputs: node_classes(int32), edge_scores(f32), edge_indices(int32, 2xN),
    // valid_adjacency(f32, CxC). JAX without x64 downcasts int64 -> int32.
    const int* node_classes = (const int*)d_in[0];
    const float* edge_scores = (const float*)d_in[1];
    const int* edge_indices = (const int*)d_in[2];
    const float* adj = (const float*)d_in[3];

    int n_nodes = in_sizes[0];
    int n_edges = in_sizes[1];
    int C = 1;
    while (C * C < in_sizes[3]) C++;  // 144 -> 12

    // Dynamic shared memory: class table + adjacency.
    int adj_off = (n_nodes + 3) & ~3;
    size_t smem_bytes = (size_t)adj_off + (size_t)C * C * sizeof(float);

    cudaFuncSetAttribute(edge_loss_kernel,
                         cudaFuncAttributeMaxDynamicSharedMemorySize,
                         (int)smem_bytes);

    int pack_blocks = (n_nodes + 255) / 256;
    pack_classes_kernel<<<pack_blocks, 256>>>(node_classes, n_nodes);

    int blocks = 296;  // ~2 waves of CTAs at 1 CTA/SM with ~100KB smem
    edge_loss_kernel<<<blocks, 512, smem_bytes>>>(edge_scores, edge_indices,
                                                  adj, n_edges, n_nodes, C);

    finalize_kernel<<<1, 1>>>((float*)d_out, n_edges);
}

// round 3
// speedup vs baseline: 1.1394x; 1.1394x over previous
#include <cuda_runtime.h>
#include <cuda_bf16.h>
#include <stdint.h>

// Scratch (no cudaMalloc allowed).
#define MAX_NODES 131072
__device__ unsigned short g_tbl[MAX_NODES];  // per-node: cls | (adj_row_mask << 4)
__device__ double g_sum;
__device__ unsigned int g_count;

// ---------------------------------------------------------------------------
// Kernel 1: build fused uint16 table; reset accumulator + completion counter.
// Each thread packs 4 nodes (int4 load -> 4x uint16 -> one 8B store).
// ---------------------------------------------------------------------------
__global__ void pack_kernel(const int* __restrict__ node_classes,
                            const float* __restrict__ adj,
                            int n_nodes, int C) {
    __shared__ unsigned int s_mask[16];
    if (threadIdx.x < (unsigned)C) {
        unsigned int m = 0;
        for (int j = 0; j < C; j++)
            m |= (adj[threadIdx.x * C + j] != 0.0f ? 1u : 0u) << j;
        s_mask[threadIdx.x] = m;
    }
    __syncthreads();

    int q = blockIdx.x * blockDim.x + threadIdx.x;
    if (q == 0) { g_sum = 0.0; g_count = 0u; }

    int base = q * 4;
    if (base + 3 < n_nodes) {
        int4 c4 = *(const int4*)(node_classes + base);
        unsigned long long w =
            (unsigned long long)((unsigned)c4.x | (s_mask[c4.x] << 4)) |
            ((unsigned long long)((unsigned)c4.y | (s_mask[c4.y] << 4)) << 16) |
            ((unsigned long long)((unsigned)c4.z | (s_mask[c4.z] << 4)) << 32) |
            ((unsigned long long)((unsigned)c4.w | (s_mask[c4.w] << 4)) << 48);
        *(unsigned long long*)(g_tbl + base) = w;
    } else if (base < n_nodes) {
        for (int i = base; i < n_nodes; i++) {
            int c = node_classes[i];
            g_tbl[i] = (unsigned short)((unsigned)c | (s_mask[c] << 4));
        }
    }
}

// ---------------------------------------------------------------------------
// Kernel 2: main edge loop + fused finalize (last block writes the mean).
//   dyn smem: n_nodes uint16 fused table.
// ---------------------------------------------------------------------------
__global__ void __launch_bounds__(1024, 1)
edge_loss_kernel(const float* __restrict__ edge_scores,
                 const int* __restrict__ edge_indices,
                 float* __restrict__ out,
                 int n_edges, int n_nodes) {
    extern __shared__ unsigned short s_tbl[];

    int tid = threadIdx.x;
    int nthreads = blockDim.x;

    // Stage fused table into shared (16B vector copies + short tail).
    int n8 = n_nodes >> 3;  // 8 uint16 per uint4
    const uint4* src16 = (const uint4*)g_tbl;
    uint4* dst16 = (uint4*)s_tbl;
    for (int i = tid; i < n8; i += nthreads) dst16[i] = src16[i];
    for (int i = (n8 << 3) + tid; i < n_nodes; i += nthreads) s_tbl[i] = g_tbl[i];
    __syncthreads();

    const int* src_idx = edge_indices;            // row 0
    const int* dst_idx = edge_indices + n_edges;  // row 1

    int nq = n_edges >> 2;  // groups of 4 edges
    int gtid = blockIdx.x * nthreads + tid;
    int gstride = gridDim.x * nthreads;
    int guard = n_nodes - 1;
    const float LN2 = 0.6931471805599453f;

    float acc = 0.0f;

    #pragma unroll 2
    for (int q = gtid; q < nq; q += gstride) {
        int4 s4 = *(const int4*)(src_idx + 4 * q);
        int4 d4 = *(const int4*)(dst_idx + 4 * q);
        float4 sc = *(const float4*)(edge_scores + 4 * q);

        unsigned ws0 = s_tbl[min(s4.x, guard)];
        unsigned wd0 = s_tbl[min(d4.x, guard)];
        unsigned ws1 = s_tbl[min(s4.y, guard)];
        unsigned wd1 = s_tbl[min(d4.y, guard)];
        unsigned ws2 = s_tbl[min(s4.z, guard)];
        unsigned wd2 = s_tbl[min(d4.z, guard)];
        unsigned ws3 = s_tbl[min(s4.w, guard)];
        unsigned wd3 = s_tbl[min(d4.w, guard)];

        // y = adj[src_cls][dst_cls]  ==  bit (4 + dst_cls) of src word
        unsigned b0 = (ws0 >> (4u + (wd0 & 15u))) & 1u;
        unsigned b1 = (ws1 >> (4u + (wd1 & 15u))) & 1u;
        unsigned b2 = (ws2 >> (4u + (wd2 & 15u))) & 1u;
        unsigned b3 = (ws3 >> (4u + (wd3 & 15u))) & 1u;

        float s0 = sc.x, s1 = sc.y, s2 = sc.z, s3 = sc.w;
        // per_edge = max(s,0) - s*y + log(1 + exp(-|s|))
        float e0 = __expf(-fabsf(s0));
        float e1 = __expf(-fabsf(s1));
        float e2 = __expf(-fabsf(s2));
        float e3 = __expf(-fabsf(s3));
        acc += fmaxf(s0, 0.0f) - (b0 ? s0 : 0.0f) + LN2 * __log2f(1.0f + e0);
        acc += fmaxf(s1, 0.0f) - (b1 ? s1 : 0.0f) + LN2 * __log2f(1.0f + e1);
        acc += fmaxf(s2, 0.0f) - (b2 ? s2 : 0.0f) + LN2 * __log2f(1.0f + e2);
        acc += fmaxf(s3, 0.0f) - (b3 ? s3 : 0.0f) + LN2 * __log2f(1.0f + e3);
    }

    // Tail edges (n_edges % 4).
    if (gtid == 0) {
        for (int e = nq << 2; e < n_edges; e++) {
            unsigned ws = s_tbl[min(src_idx[e], guard)];
            unsigned wd = s_tbl[min(dst_idx[e], guard)];
            unsigned b = (ws >> (4u + (wd & 15u))) & 1u;
            float s = edge_scores[e];
            acc += fmaxf(s, 0.0f) - (b ? s : 0.0f) +
                   LN2 * __log2f(1.0f + __expf(-fabsf(s)));
        }
    }

    // Block reduction: warp shuffle -> shared -> one double atomic per block.
    __shared__ float red[32];
    int lane = tid & 31;
    int wid = tid >> 5;
    #pragma unroll
    for (int off = 16; off > 0; off >>= 1)
        acc += __shfl_xor_sync(0xFFFFFFFFu, acc, off);
    if (lane == 0) red[wid] = acc;
    __syncthreads();
    if (wid == 0) {
        int nw = nthreads >> 5;
        float v = (lane < nw) ? red[lane] : 0.0f;
        #pragma unroll
        for (int off = 16; off > 0; off >>= 1)
            v += __shfl_xor_sync(0xFFFFFFFFu, v, off);
        if (lane == 0) {
            atomicAdd(&g_sum, (double)v);
            __threadfence();
            unsigned done = atomicAdd(&g_count, 1u);
            if (done == gridDim.x - 1) {
                double total = *((volatile double*)&g_sum);
                out[0] = (float)(total / (double)n_edges);
            }
        }
    }
}

extern "C" void kernel_launch(void* const* d_in, const int* in_sizes, int n_in,
                              void* d_out, int out_size) {
    // Inputs: node_classes(int32), edge_scores(f32), edge_indices(int32, 2xN),
    // valid_adjacency(f32, CxC).
    const int* node_classes = (const int*)d_in[0];
    const float* edge_scores = (const float*)d_in[1];
    const int* edge_indices = (const int*)d_in[2];
    const float* adj = (const float*)d_in[3];

    int n_nodes = in_sizes[0];
    int n_edges = in_sizes[1];
    int C = 1;
    while (C * C < in_sizes[3]) C++;  // 144 -> 12

    size_t smem_bytes = (size_t)n_nodes * sizeof(unsigned short);

    cudaFuncSetAttribute(edge_loss_kernel,
                         cudaFuncAttributeMaxDynamicSharedMemorySize,
                         (int)smem_bytes);

    // One persistent CTA per SM (host-side query; runs at capture time only).
    int nsm = 148;
    cudaDeviceGetAttribute(&nsm, cudaDevAttrMultiProcessorCount, 0);

    int pack_threads = 256;
    int pack_blocks = ((n_nodes + 3) / 4 + pack_threads - 1) / pack_threads;
    pack_kernel<<<pack_blocks, pack_threads>>>(node_classes, adj, n_nodes, C);

    edge_loss_kernel<<<nsm, 1024, smem_bytes>>>(edge_scores, edge_indices,
                                                (float*)d_out, n_edges, n_nodes);
}